// round 13
// baseline (speedup 1.0000x reference)
#include <cuda_runtime.h>

// LocalMGDCF: out = BETA*x + sum_{k=1..4} ALPHA^k (P^k x),  P = D^-1 A (mean-aggr).
// ZERO __device__ globals. CSR (cursor+col+spare) packed into cols 112..127 of
// nodes 0..49999 inside d_out. One persistent kernel (391 blocks, co-resident via
// __launch_bounds__(256,3)); software grid barrier. In-place chunked Horner
// (16 cols/chunk, 2-phase hops); chunk 7 iterates in region 6 before chunk 6,
// finals deferred in registers and written over the CSR at the very end.
// R12 change: 4-lane-subgroup coalesced gathers/stores (64B contiguous per
// neighbor), cooperative col loads, hoisted per-node CSR bounds, .cg gathers.

#define NN 100000
#define EE 600000
#define DDIM 128
#define ALPHA_C 0.1f
#define BETA_C 0.9f

#define TPB 256
#define NBLK ((NN + TPB - 1) / TPB)    // 391; co-resident: 148 SMs * 3 = 444
#define COL_BASE   NN                  // csr-space index of col[] start
#define SPARE_BASE 700000              // cnt, gen
#define AUX_BASE   (SPARE_BASE + 8)    // per-block scan totals (NBLK words)

// csr-space word i -> word index into d_out (int view). Region = cols 112..127
// of nodes 0..49999 (800000 words available, ~700407 used).
__device__ __forceinline__ int csr_word(int i) {
    return ((i >> 4) * DDIM) + 112 + (i & 15);
}

__device__ __forceinline__ int eidx(const void* p, int e, bool is64) {
    int v = is64 ? (int)((const long long*)p)[e] : ((const int*)p)[e];
    return min(max(v, 0), NN - 1);   // clamp: all downstream accesses in-bounds
}

// software grid barrier (all blocks co-resident by construction)
__device__ __forceinline__ void gbar(int* cnt, volatile int* gen) {
    __syncthreads();
    if (threadIdx.x == 0) {
        __threadfence();
        int g = *gen;
        if (atomicAdd(cnt, 1) == NBLK - 1) {
            atomicExch(cnt, 0);
            __threadfence();
            atomicAdd((int*)gen, 1);
        } else {
            while (*gen == g) __nanosleep(64);
        }
        __threadfence();
    }
    __syncthreads();
}

__global__ void init_kernel(float* out) {
    int* oi = (int*)out;
    if (threadIdx.x < 8) oi[csr_word(SPARE_BASE + (int)threadIdx.x)] = 0;
}

__global__ __launch_bounds__(TPB, 3)
void mgdcf_kernel(const float* __restrict__ x, const void* __restrict__ src,
                  const void* __restrict__ dst, float* out)
{
    int* oi = (int*)out;
    const int T = NBLK * TPB;
    const int t = blockIdx.x * TPB + threadIdx.x;

    int*          cnt = &oi[csr_word(SPARE_BASE)];
    volatile int* gen = (volatile int*)&oi[csr_word(SPARE_BASE + 1)];

    // dtype probe: redundant per-thread, no communication. int64 indices < 1e5
    // have all-zero high words; int32 -> odd words are random values.
    const unsigned* sw = (const unsigned*)src;
    unsigned pv = 0;
    #pragma unroll
    for (int q = 0; q < 8; q++) pv |= __ldg(&sw[2 * q + 1]);
    const bool is64 = (pv == 0u);

    // ---- CSR build ----
    for (int i = t; i < NN; i += T) oi[csr_word(i)] = 0;          // deg := 0
    gbar(cnt, gen);

    for (int e = t; e < EE; e += T)                               // histogram
        atomicAdd(&oi[csr_word(eidx(dst, e, is64))], 1);
    gbar(cnt, gen);

    // exclusive scan (blocked mapping: thread t owns node t), deg -> cursor
    __shared__ int wsum[8];
    __shared__ int sbase;
    const int lane = threadIdx.x & 31, wid = threadIdx.x >> 5;
    int v = (t < NN) ? oi[csr_word(t)] : 0;
    int incl = v;
    #pragma unroll
    for (int o = 1; o < 32; o <<= 1) {
        int tt = __shfl_up_sync(~0u, incl, o);
        if (lane >= o) incl += tt;
    }
    if (lane == 31) wsum[wid] = incl;
    __syncthreads();
    if (wid == 0 && lane < 8) {
        int ws = wsum[lane];
        #pragma unroll
        for (int o = 1; o < 8; o <<= 1) {
            int tt = __shfl_up_sync(0xFFu, ws, o);
            if (lane >= o) ws += tt;
        }
        wsum[lane] = ws;
    }
    __syncthreads();
    incl += wid ? wsum[wid - 1] : 0;
    if (threadIdx.x == 0) oi[csr_word(AUX_BASE + blockIdx.x)] = wsum[7];
    gbar(cnt, gen);
    {
        int part = 0;
        for (int j = threadIdx.x; j < blockIdx.x; j += TPB)
            part += oi[csr_word(AUX_BASE + j)];
        #pragma unroll
        for (int o = 16; o > 0; o >>= 1) part += __shfl_xor_sync(~0u, part, o);
        __syncthreads();              // wsum reuse
        if (lane == 0) wsum[wid] = part;
        __syncthreads();
        if (threadIdx.x == 0) {
            int s2 = 0;
            #pragma unroll
            for (int q = 0; q < 8; q++) s2 += wsum[q];
            sbase = s2;
        }
        __syncthreads();
    }
    if (t < NN) oi[csr_word(t)] = sbase + incl - v;               // cursor=rowptr
    gbar(cnt, gen);

    for (int e = t; e < EE; e += T) {                             // fill
        int d = eidx(dst, e, is64);
        int s = eidx(src, e, is64);
        int p = atomicAdd(&oi[csr_word(d)], 1);
        oi[csr_word(COL_BASE + p)] = s;
    }
    gbar(cnt, gen);

    // ---- hop engine: 4-lane subgroup per node, 4 nodes per subgroup ----
    const int nb = t & ~3;                       // first node of this subgroup
    const int sl = t & 3;                        // lane within subgroup
    const unsigned smask = 0xFu << ((threadIdx.x & 31) & ~3);

    // per-node bounds (post-fill cursor[n] == rowptr[n+1]); hoisted once
    int rs4[4], re4[4];
    float ai4[4];
    {
        int prev = (nb > 0) ? __ldcg((const int*)&oi[csr_word(nb - 1)]) : 0;
        #pragma unroll
        for (int q = 0; q < 4; q++) {
            int n = nb + q;
            int cur = (n < NN) ? __ldcg((const int*)&oi[csr_word(n)]) : prev;
            rs4[q] = prev;
            re4[q] = cur;
            int dg = cur - prev;
            ai4[q] = (dg > 0) ? (ALPHA_C / (float)dg) : 0.f;
            prev = cur;
        }
    }

    float4 def[4];
    #pragma unroll
    for (int q = 0; q < 4; q++) def[q] = make_float4(0.f, 0.f, 0.f, 0.f);

    // chunk order: 0..5, 7 (h-iterate in region 6), 6 (in-place, last)
    #pragma unroll 1
    for (int ci = 0; ci < 8; ci++) {
        const int c  = (ci < 6) ? ci : (ci == 6 ? 7 : 6);
        const int hb = (c == 7) ? 6 : c;
        #pragma unroll 1
        for (int k = 1; k <= 4; k++) {
            const float4* Gf4 = (k == 1) ? ((const float4*)x + c * 4)
                                         : ((const float4*)out + hb * 4);
            float4 acc[4];
            #pragma unroll
            for (int q = 0; q < 4; q++) {
                acc[q] = make_float4(0.f, 0.f, 0.f, 0.f);
                int n = nb + q;
                if (n >= NN) continue;           // uniform across the subgroup
                for (int j = rs4[q]; j < re4[q]; j += 4) {
                    int cnt = re4[q] - j;
                    if (cnt > 4) cnt = 4;
                    int mycol = (sl < cnt)
                        ? __ldg((const int*)&oi[csr_word(COL_BASE + j + sl)]) : 0;
                    #pragma unroll
                    for (int jj = 0; jj < 4; jj++) {
                        if (jj < cnt) {
                            int s = __shfl_sync(smask, mycol, jj, 4);
                            float4 vv = __ldcg(Gf4 + s * 32 + sl);
                            acc[q].x += vv.x; acc[q].y += vv.y;
                            acc[q].z += vv.z; acc[q].w += vv.w;
                        }
                    }
                }
            }
            // barrier before writing iff write region == gather region
            if ((k == 2) || (k == 3) || (k == 4 && c != 7)) gbar(cnt, gen);

            const float cx   = (k == 4) ? BETA_C : 1.0f;
            const int   wcol = (k < 4) ? hb : c;
            #pragma unroll
            for (int q = 0; q < 4; q++) {
                int n = nb + q;
                if (n >= NN) continue;
                float4 xv = __ldg((const float4*)x + n * 32 + c * 4 + sl);
                float4 vv = make_float4(cx * xv.x + ai4[q] * acc[q].x,
                                        cx * xv.y + ai4[q] * acc[q].y,
                                        cx * xv.z + ai4[q] * acc[q].z,
                                        cx * xv.w + ai4[q] * acc[q].w);
                if (k == 4 && c == 7 && n < 50000) {
                    def[q] = vv;                 // defer over CSR
                } else {
                    ((float4*)out)[n * 32 + wcol * 4 + sl] = vv;
                }
            }
            if (!(c == 6 && k == 4)) gbar(cnt, gen);   // last phase: no barrier
        }
    }

    // final: deferred chunk-7 outputs overwrite the CSR. Safe: the last CSR
    // reads happen in the chunk-6 k=4 gather, which completes before that
    // phase's pre-write barrier, which precedes this store.
    #pragma unroll
    for (int q = 0; q < 4; q++) {
        int n = nb + q;
        if (n < 50000)
            ((float4*)out)[n * 32 + 28 + sl] = def[q];
    }
}

extern "C" void kernel_launch(void* const* d_in, const int* in_sizes, int n_in,
                              void* d_out, int out_size) {
    const float* x   = (const float*)d_in[0];
    const void*  src = d_in[1];
    const void*  dst = d_in[2];
    float*       out = (float*)d_out;
    (void)in_sizes; (void)n_in; (void)out_size;

    init_kernel<<<1, 32>>>(out);
    mgdcf_kernel<<<NBLK, TPB>>>(x, src, dst, out);
}

// round 14
// speedup vs baseline: 1.7117x; 1.7117x over previous
#include <cuda_runtime.h>

// LocalMGDCF: out = BETA*x + sum_{k=1..4} ALPHA^k (P^k x),  P = D^-1 A (mean-aggr).
// ZERO __device__ globals. CSR (cursor+col+spare) packed into cols 112..127 of
// nodes 0..49999 inside d_out. One persistent kernel (391 blocks, co-resident via
// __launch_bounds__(256,3)); TWO-LEVEL tree grid barrier. In-place chunked Horner
// (16 cols/chunk, 2-phase hops); chunk 7 iterates in region 6 before chunk 6,
// finals deferred in registers and written over the CSR at the very end.
// R14: revert to R11 divergent per-thread gather (R12 subgroup variant regressed
// 2x on instruction issue); add tree barrier + col prefetch.

#define NN 100000
#define EE 600000
#define DDIM 128
#define ALPHA_C 0.1f
#define BETA_C 0.9f

#define TPB 256
#define NBLK ((NN + TPB - 1) / TPB)    // 391; co-resident: 148 SMs * 3 = 444
#define COL_BASE   NN                  // csr-space index of col[] start
#define SPARE_BASE 700000              // root cnt(+0), gen(+1), group cnts(+32+g*32)
#define AUX_BASE   (SPARE_BASE + 1100) // per-block scan totals (NBLK words)

// csr-space word i -> word index into d_out (int view). Region = cols 112..127
// of nodes 0..49999 (800000 words available).
__device__ __forceinline__ int csr_word(int i) {
    return ((i >> 4) * DDIM) + 112 + (i & 15);
}

__device__ __forceinline__ int eidx(const void* p, int e, bool is64) {
    int v = is64 ? (int)((const long long*)p)[e] : ((const int*)p)[e];
    return min(max(v, 0), NN - 1);   // clamp: all downstream accesses in-bounds
}

// two-level software grid barrier (all blocks co-resident by construction).
// 32 groups (block % 32); last arrival per group arrives at root; last root
// arrival bumps gen. ~13 concurrent atomics per group address instead of 391
// serialized on one address.
__device__ __forceinline__ void gbar(int* oi) {
    __syncthreads();
    if (threadIdx.x == 0) {
        __threadfence();
        volatile int* gen = (volatile int*)&oi[csr_word(SPARE_BASE + 1)];
        int g0 = *gen;
        int grp = blockIdx.x & 31;
        int expect = (NBLK - grp + 31) >> 5;     // 13 for grp<7, else 12
        int* gcnt = &oi[csr_word(SPARE_BASE + 32 + grp * 32)];
        if (atomicAdd(gcnt, 1) == expect - 1) {
            atomicExch(gcnt, 0);
            int* root = &oi[csr_word(SPARE_BASE)];
            if (atomicAdd(root, 1) == 31) {
                atomicExch(root, 0);
                __threadfence();
                atomicAdd((int*)gen, 1);
            }
        }
        while (*gen == g0) __nanosleep(64);
        __threadfence();
    }
    __syncthreads();
}

__global__ void init_kernel(float* out) {
    int* oi = (int*)out;
    int i = (int)threadIdx.x;
    if (i < 32) oi[csr_word(SPARE_BASE + 32 + i * 32)] = 0;   // group counters
    else if (i == 32) oi[csr_word(SPARE_BASE)] = 0;           // root
    else if (i == 33) oi[csr_word(SPARE_BASE + 1)] = 0;       // gen
}

__global__ __launch_bounds__(TPB, 3)
void mgdcf_kernel(const float* __restrict__ x, const void* __restrict__ src,
                  const void* __restrict__ dst, float* out)
{
    int* oi = (int*)out;
    const int T = NBLK * TPB;
    const int t = blockIdx.x * TPB + threadIdx.x;

    // dtype probe: redundant per-thread, no communication. int64 indices < 1e5
    // have all-zero high words; int32 -> odd words are random values.
    const unsigned* sw = (const unsigned*)src;
    unsigned pv = 0;
    #pragma unroll
    for (int q = 0; q < 8; q++) pv |= __ldg(&sw[2 * q + 1]);
    const bool is64 = (pv == 0u);

    // ---- CSR build ----
    for (int i = t; i < NN; i += T) oi[csr_word(i)] = 0;          // deg := 0
    gbar(oi);

    for (int e = t; e < EE; e += T)                               // histogram
        atomicAdd(&oi[csr_word(eidx(dst, e, is64))], 1);
    gbar(oi);

    // exclusive scan (blocked mapping: thread t owns node t), deg -> cursor
    __shared__ int wsum[8];
    __shared__ int sbase;
    const int lane = threadIdx.x & 31, wid = threadIdx.x >> 5;
    int v = (t < NN) ? __ldcg((const int*)&oi[csr_word(t)]) : 0;
    int incl = v;
    #pragma unroll
    for (int o = 1; o < 32; o <<= 1) {
        int tt = __shfl_up_sync(~0u, incl, o);
        if (lane >= o) incl += tt;
    }
    if (lane == 31) wsum[wid] = incl;
    __syncthreads();
    if (wid == 0 && lane < 8) {
        int ws = wsum[lane];
        #pragma unroll
        for (int o = 1; o < 8; o <<= 1) {
            int tt = __shfl_up_sync(0xFFu, ws, o);
            if (lane >= o) ws += tt;
        }
        wsum[lane] = ws;
    }
    __syncthreads();
    incl += wid ? wsum[wid - 1] : 0;
    if (threadIdx.x == 0) oi[csr_word(AUX_BASE + blockIdx.x)] = wsum[7];
    gbar(oi);
    {
        int part = 0;
        for (int j = threadIdx.x; j < blockIdx.x; j += TPB)
            part += __ldcg((const int*)&oi[csr_word(AUX_BASE + j)]);
        #pragma unroll
        for (int o = 16; o > 0; o >>= 1) part += __shfl_xor_sync(~0u, part, o);
        __syncthreads();              // wsum reuse
        if (lane == 0) wsum[wid] = part;
        __syncthreads();
        if (threadIdx.x == 0) {
            int s2 = 0;
            #pragma unroll
            for (int q = 0; q < 8; q++) s2 += wsum[q];
            sbase = s2;
        }
        __syncthreads();
    }
    if (t < NN) oi[csr_word(t)] = sbase + incl - v;               // cursor=rowptr
    gbar(oi);

    for (int e = t; e < EE; e += T) {                             // fill
        int d = eidx(dst, e, is64);
        int s = eidx(src, e, is64);
        int p = atomicAdd(&oi[csr_word(d)], 1);
        oi[csr_word(COL_BASE + p)] = s;
    }
    gbar(oi);

    // per-node bounds: post-fill cursor[n] == rowptr[n+1]
    const bool has = (t < NN);
    int rs = 0, re = 0;
    float ainv = 0.f;
    if (has) {
        re = __ldcg((const int*)&oi[csr_word(t)]);
        rs = t ? __ldcg((const int*)&oi[csr_word(t - 1)]) : 0;
        int dg = re - rs;
        ainv = (dg > 0) ? (ALPHA_C / (float)dg) : 0.f;
    }

    float def0[16];
    #pragma unroll
    for (int q = 0; q < 16; q++) def0[q] = 0.f;

    // chunk order: 0..5, 7 (h-iterate in region 6), 6 (in-place, last)
    #pragma unroll 1
    for (int ci = 0; ci < 8; ci++) {
        const int c  = (ci < 6) ? ci : (ci == 6 ? 7 : 6);
        const int hb = (c == 7) ? 6 : c;
        #pragma unroll 1
        for (int k = 1; k <= 4; k++) {
            float acc[16];
            #pragma unroll
            for (int q = 0; q < 16; q++) acc[q] = 0.f;
            if (has) {
                const float4* Gf4 = (k == 1) ? ((const float4*)x + c * 4)
                                             : ((const float4*)out + hb * 4);
                // depth-1 col prefetch: next index loads while current row streams
                int cnext = (rs < re) ? __ldg((const int*)&oi[csr_word(COL_BASE + rs)]) : 0;
                for (int j = rs; j < re; j++) {
                    int s = cnext;
                    if (j + 1 < re)
                        cnext = __ldg((const int*)&oi[csr_word(COL_BASE + j + 1)]);
                    const float4* r = Gf4 + (size_t)s * 32;
                    float4 a0 = __ldcg(r + 0), a1 = __ldcg(r + 1);
                    float4 a2 = __ldcg(r + 2), a3 = __ldcg(r + 3);
                    acc[0]  += a0.x; acc[1]  += a0.y; acc[2]  += a0.z; acc[3]  += a0.w;
                    acc[4]  += a1.x; acc[5]  += a1.y; acc[6]  += a1.z; acc[7]  += a1.w;
                    acc[8]  += a2.x; acc[9]  += a2.y; acc[10] += a2.z; acc[11] += a2.w;
                    acc[12] += a3.x; acc[13] += a3.y; acc[14] += a3.z; acc[15] += a3.w;
                }
            }
            // barrier before writing iff write region == gather region
            if ((k == 2) || (k == 3) || (k == 4 && c != 7)) gbar(oi);
            if (has) {
                const float cx = (k == 4) ? BETA_C : 1.0f;
                const float4* xr = (const float4*)(x + (size_t)t * DDIM + c * 16);
                float4 x0 = __ldg(xr + 0), x1 = __ldg(xr + 1);
                float4 x2 = __ldg(xr + 2), x3 = __ldg(xr + 3);
                float vv[16];
                vv[0]  = cx * x0.x + ainv * acc[0];  vv[1]  = cx * x0.y + ainv * acc[1];
                vv[2]  = cx * x0.z + ainv * acc[2];  vv[3]  = cx * x0.w + ainv * acc[3];
                vv[4]  = cx * x1.x + ainv * acc[4];  vv[5]  = cx * x1.y + ainv * acc[5];
                vv[6]  = cx * x1.z + ainv * acc[6];  vv[7]  = cx * x1.w + ainv * acc[7];
                vv[8]  = cx * x2.x + ainv * acc[8];  vv[9]  = cx * x2.y + ainv * acc[9];
                vv[10] = cx * x2.z + ainv * acc[10]; vv[11] = cx * x2.w + ainv * acc[11];
                vv[12] = cx * x3.x + ainv * acc[12]; vv[13] = cx * x3.y + ainv * acc[13];
                vv[14] = cx * x3.z + ainv * acc[14]; vv[15] = cx * x3.w + ainv * acc[15];

                if (k == 4 && c == 7 && t < 50000) {
                    #pragma unroll
                    for (int q = 0; q < 16; q++) def0[q] = vv[q];   // defer over CSR
                } else {
                    const int wcol = (k < 4) ? hb : c;
                    float4* w = (float4*)(out + (size_t)t * DDIM + wcol * 16);
                    w[0] = make_float4(vv[0],  vv[1],  vv[2],  vv[3]);
                    w[1] = make_float4(vv[4],  vv[5],  vv[6],  vv[7]);
                    w[2] = make_float4(vv[8],  vv[9],  vv[10], vv[11]);
                    w[3] = make_float4(vv[12], vv[13], vv[14], vv[15]);
                }
            }
            if (!(c == 6 && k == 4)) gbar(oi);   // last phase: no barrier
        }
    }

    // final: deferred chunk-7 outputs overwrite the CSR. Safe: the last CSR
    // reads happen in the chunk-6 k=4 gather, which completes before that
    // phase's pre-write barrier, which precedes this store.
    if (t < 50000) {
        float4* w = (float4*)(out + (size_t)t * DDIM + 112);
        w[0] = make_float4(def0[0],  def0[1],  def0[2],  def0[3]);
        w[1] = make_float4(def0[4],  def0[5],  def0[6],  def0[7]);
        w[2] = make_float4(def0[8],  def0[9],  def0[10], def0[11]);
        w[3] = make_float4(def0[12], def0[13], def0[14], def0[15]);
    }
}

extern "C" void kernel_launch(void* const* d_in, const int* in_sizes, int n_in,
                              void* d_out, int out_size) {
    const float* x   = (const float*)d_in[0];
    const void*  src = d_in[1];
    const void*  dst = d_in[2];
    float*       out = (float*)d_out;
    (void)in_sizes; (void)n_in; (void)out_size;

    init_kernel<<<1, 64>>>(out);
    mgdcf_kernel<<<NBLK, TPB>>>(x, src, dst, out);
}

// round 15
// speedup vs baseline: 2.2513x; 1.3152x over previous
#include <cuda_runtime.h>

// LocalMGDCF: out = BETA*x + sum_{k=1..4} ALPHA^k (P^k x),  P = D^-1 A (mean-aggr).
// ZERO __device__ globals. CSR (cursor+col+spare) packed into cols 112..127 of
// nodes 0..49999 inside d_out. One persistent kernel; software grid barrier.
// In-place chunked Horner (16 cols/chunk, 2-phase hops); chunk 7 iterates in
// region 6 before chunk 6, finals deferred in registers, written over CSR last.
// R15: TWO threads per node (8 cols each) -> 200K threads, TPB=512,
// launch_bounds(512,3) => 75% occupancy (vs 33%), to hide gather latency.

#define NN 100000
#define EE 600000
#define ALPHA_C 0.1f
#define BETA_C 0.9f

#define TPB 512
#define NTHREADS (2 * NN)
#define NBLK ((NTHREADS + TPB - 1) / TPB)   // 391; co-resident: 148 SMs * 3 = 444
#define COL_BASE   NN                       // csr-space index of col[] start
#define SPARE_BASE 700000                   // cnt, gen
#define AUX_BASE   (SPARE_BASE + 8)         // per-block scan totals (NBLK words)

// csr-space word i -> word index into d_out (int view). Region = cols 112..127
// of nodes 0..49999.
__device__ __forceinline__ int csr_word(int i) {
    return ((i >> 4) * 128) + 112 + (i & 15);
}

__device__ __forceinline__ int eidx(const void* p, int e, bool is64) {
    int v = is64 ? (int)((const long long*)p)[e] : ((const int*)p)[e];
    return min(max(v, 0), NN - 1);   // clamp: all downstream accesses in-bounds
}

// simple software grid barrier (all blocks co-resident by construction)
__device__ __forceinline__ void gbar(int* oi) {
    __syncthreads();
    if (threadIdx.x == 0) {
        int* cnt = &oi[csr_word(SPARE_BASE)];
        volatile int* gen = (volatile int*)&oi[csr_word(SPARE_BASE + 1)];
        __threadfence();
        int g = *gen;
        if (atomicAdd(cnt, 1) == NBLK - 1) {
            atomicExch(cnt, 0);
            __threadfence();
            atomicAdd((int*)gen, 1);
        } else {
            while (*gen == g) __nanosleep(64);
        }
        __threadfence();
    }
    __syncthreads();
}

__global__ void init_kernel(float* out) {
    int* oi = (int*)out;
    if (threadIdx.x < 8) oi[csr_word(SPARE_BASE + (int)threadIdx.x)] = 0;
}

__global__ __launch_bounds__(TPB, 3)
void mgdcf_kernel(const float* __restrict__ x, const void* __restrict__ src,
                  const void* __restrict__ dst, float* out)
{
    int* oi = (int*)out;
    const int T = NBLK * TPB;                 // 200192
    const int t = blockIdx.x * TPB + threadIdx.x;

    // dtype probe: redundant per-thread. int64 indices < 1e5 have all-zero
    // high words; int32 -> odd words are random values.
    const unsigned* sw = (const unsigned*)src;
    unsigned pv = 0;
    #pragma unroll
    for (int q = 0; q < 8; q++) pv |= __ldg(&sw[2 * q + 1]);
    const bool is64 = (pv == 0u);

    // ---- CSR build ----
    for (int i = t; i < NN; i += T) oi[csr_word(i)] = 0;          // deg := 0
    gbar(oi);

    for (int e = t; e < EE; e += T)                               // histogram
        atomicAdd(&oi[csr_word(eidx(dst, e, is64))], 1);
    gbar(oi);

    // exclusive scan (blocked: thread t owns node t; blocks 196+ idle here)
    __shared__ int wsum[16];
    __shared__ int sbase;
    const int lane = threadIdx.x & 31, wid = threadIdx.x >> 5;
    int v = (t < NN) ? __ldcg((const int*)&oi[csr_word(t)]) : 0;
    int incl = v;
    #pragma unroll
    for (int o = 1; o < 32; o <<= 1) {
        int tt = __shfl_up_sync(~0u, incl, o);
        if (lane >= o) incl += tt;
    }
    if (lane == 31) wsum[wid] = incl;
    __syncthreads();
    if (wid == 0) {
        int ws = (lane < 16) ? wsum[lane] : 0;
        #pragma unroll
        for (int o = 1; o < 16; o <<= 1) {
            int tt = __shfl_up_sync(~0u, ws, o);
            if (lane >= o) ws += tt;
        }
        if (lane < 16) wsum[lane] = ws;
    }
    __syncthreads();
    incl += wid ? wsum[wid - 1] : 0;
    if (threadIdx.x == 0) oi[csr_word(AUX_BASE + blockIdx.x)] = wsum[15];
    gbar(oi);
    {
        int part = 0;
        for (int j = threadIdx.x; j < blockIdx.x; j += TPB)
            part += __ldcg((const int*)&oi[csr_word(AUX_BASE + j)]);
        #pragma unroll
        for (int o = 16; o > 0; o >>= 1) part += __shfl_xor_sync(~0u, part, o);
        __syncthreads();              // wsum reuse
        if (lane == 0) wsum[wid] = part;
        __syncthreads();
        if (threadIdx.x == 0) {
            int s2 = 0;
            #pragma unroll
            for (int q = 0; q < 16; q++) s2 += wsum[q];
            sbase = s2;
        }
        __syncthreads();
    }
    if (t < NN) oi[csr_word(t)] = sbase + incl - v;               // cursor=rowptr
    gbar(oi);

    for (int e = t; e < EE; e += T) {                             // fill
        int d = eidx(dst, e, is64);
        int s = eidx(src, e, is64);
        int p = atomicAdd(&oi[csr_word(d)], 1);
        oi[csr_word(COL_BASE + p)] = s;
    }
    gbar(oi);

    // ---- hop engine: 2 threads per node, 8 cols (2 float4) each ----
    const int node = t >> 1;
    const int hf   = t & 1;                  // which half of the 16-col chunk
    const bool has = (node < NN);

    int rs = 0, re = 0;
    float ainv = 0.f;
    if (has) {
        re = __ldcg((const int*)&oi[csr_word(node)]);
        rs = node ? __ldcg((const int*)&oi[csr_word(node - 1)]) : 0;
        int dg = re - rs;
        ainv = (dg > 0) ? (ALPHA_C / (float)dg) : 0.f;
    }

    float def[8];
    #pragma unroll
    for (int q = 0; q < 8; q++) def[q] = 0.f;

    // chunk order: 0..5, 7 (h-iterate in region 6), 6 (in-place, last)
    #pragma unroll 1
    for (int ci = 0; ci < 8; ci++) {
        const int c  = (ci < 6) ? ci : (ci == 6 ? 7 : 6);
        const int hb = (c == 7) ? 6 : c;
        #pragma unroll 1
        for (int k = 1; k <= 4; k++) {
            float acc[8];
            #pragma unroll
            for (int q = 0; q < 8; q++) acc[q] = 0.f;
            if (has) {
                const float4* G = (k == 1)
                    ? ((const float4*)x)   + c  * 4 + hf * 2
                    : ((const float4*)out) + hb * 4 + hf * 2;
                for (int j = rs; j < re; j++) {
                    int s = __ldg((const int*)&oi[csr_word(COL_BASE + j)]);
                    const float4* r = G + (size_t)s * 32;
                    float4 a0 = __ldcg(r + 0);
                    float4 a1 = __ldcg(r + 1);
                    acc[0] += a0.x; acc[1] += a0.y; acc[2] += a0.z; acc[3] += a0.w;
                    acc[4] += a1.x; acc[5] += a1.y; acc[6] += a1.z; acc[7] += a1.w;
                }
            }
            // barrier before writing iff write region == gather region
            if ((k == 2) || (k == 3) || (k == 4 && c != 7)) gbar(oi);
            if (has) {
                const float cx = (k == 4) ? BETA_C : 1.0f;
                const float4* xr = ((const float4*)x) + (size_t)node * 32 + c * 4 + hf * 2;
                float4 x0 = __ldg(xr + 0), x1 = __ldg(xr + 1);
                float vv[8];
                vv[0] = cx * x0.x + ainv * acc[0];
                vv[1] = cx * x0.y + ainv * acc[1];
                vv[2] = cx * x0.z + ainv * acc[2];
                vv[3] = cx * x0.w + ainv * acc[3];
                vv[4] = cx * x1.x + ainv * acc[4];
                vv[5] = cx * x1.y + ainv * acc[5];
                vv[6] = cx * x1.z + ainv * acc[6];
                vv[7] = cx * x1.w + ainv * acc[7];

                if (k == 4 && c == 7 && node < 50000) {
                    #pragma unroll
                    for (int q = 0; q < 8; q++) def[q] = vv[q];   // defer over CSR
                } else {
                    const int wcol = (k < 4) ? hb : c;
                    float4* w = ((float4*)out) + (size_t)node * 32 + wcol * 4 + hf * 2;
                    w[0] = make_float4(vv[0], vv[1], vv[2], vv[3]);
                    w[1] = make_float4(vv[4], vv[5], vv[6], vv[7]);
                }
            }
            if (!(c == 6 && k == 4)) gbar(oi);   // last phase: no barrier
        }
    }

    // final: deferred chunk-7 outputs overwrite the CSR. Safe: the last CSR
    // reads happen in the chunk-6 k=4 gather, which completes before that
    // phase's pre-write barrier, which precedes this store.
    if (node < 50000) {
        float4* w = ((float4*)out) + (size_t)node * 32 + 28 + hf * 2;
        w[0] = make_float4(def[0], def[1], def[2], def[3]);
        w[1] = make_float4(def[4], def[5], def[6], def[7]);
    }
}

extern "C" void kernel_launch(void* const* d_in, const int* in_sizes, int n_in,
                              void* d_out, int out_size) {
    const float* x   = (const float*)d_in[0];
    const void*  src = d_in[1];
    const void*  dst = d_in[2];
    float*       out = (float*)d_out;
    (void)in_sizes; (void)n_in; (void)out_size;

    init_kernel<<<1, 32>>>(out);
    mgdcf_kernel<<<NBLK, TPB>>>(x, src, dst, out);
}

// round 16
// speedup vs baseline: 2.5060x; 1.1132x over previous
#include <cuda_runtime.h>
#include <cuda_bf16.h>

// LocalMGDCF: out = BETA*x + sum_{k=1..4} ALPHA^k (P^k x),  P = D^-1 A (mean-aggr).
// ZERO __device__ globals. CSR (cursor+col+spare) packed into cols 112..127 of
// nodes 0..49999 inside d_out. One persistent kernel; software grid barrier.
// In-place chunked Horner (16 cols/chunk, 2-phase hops); chunk 7 iterates in
// region 6 before chunk 6, finals deferred in registers, written over CSR last.
// R15: two threads/node (8 cols each), 200K threads, occ ~66%.
// R16: h-iterates stored as bf16 (16 cols = 32B, lower half of the chunk
// region) -> hops 2..4 gather ONE 16B LDG per thread per neighbor (halves the
// divergent-access floor for 24/32 phases). Accumulation + finals stay fp32.

#define NN 100000
#define EE 600000
#define ALPHA_C 0.1f
#define BETA_C 0.9f

#define TPB 512
#define NTHREADS (2 * NN)
#define NBLK ((NTHREADS + TPB - 1) / TPB)   // 391; co-resident: 148 SMs * 3 = 444
#define COL_BASE   NN                       // csr-space index of col[] start
#define SPARE_BASE 700000                   // cnt, gen
#define AUX_BASE   (SPARE_BASE + 8)         // per-block scan totals (NBLK words)

// csr-space word i -> word index into d_out (int view). Region = cols 112..127
// of nodes 0..49999.
__device__ __forceinline__ int csr_word(int i) {
    return ((i >> 4) * 128) + 112 + (i & 15);
}

__device__ __forceinline__ int eidx(const void* p, int e, bool is64) {
    int v = is64 ? (int)((const long long*)p)[e] : ((const int*)p)[e];
    return min(max(v, 0), NN - 1);   // clamp: all downstream accesses in-bounds
}

// simple software grid barrier (all blocks co-resident by construction)
__device__ __forceinline__ void gbar(int* oi) {
    __syncthreads();
    if (threadIdx.x == 0) {
        int* cnt = &oi[csr_word(SPARE_BASE)];
        volatile int* gen = (volatile int*)&oi[csr_word(SPARE_BASE + 1)];
        __threadfence();
        int g = *gen;
        if (atomicAdd(cnt, 1) == NBLK - 1) {
            atomicExch(cnt, 0);
            __threadfence();
            atomicAdd((int*)gen, 1);
        } else {
            while (*gen == g) __nanosleep(64);
        }
        __threadfence();
    }
    __syncthreads();
}

__global__ void init_kernel(float* out) {
    int* oi = (int*)out;
    if (threadIdx.x < 8) oi[csr_word(SPARE_BASE + (int)threadIdx.x)] = 0;
}

__global__ __launch_bounds__(TPB, 3)
void mgdcf_kernel(const float* __restrict__ x, const void* __restrict__ src,
                  const void* __restrict__ dst, float* out)
{
    int* oi = (int*)out;
    const int T = NBLK * TPB;                 // 200192
    const int t = blockIdx.x * TPB + threadIdx.x;

    // dtype probe: redundant per-thread. int64 indices < 1e5 have all-zero
    // high words; int32 -> odd words are random values.
    const unsigned* sw = (const unsigned*)src;
    unsigned pv = 0;
    #pragma unroll
    for (int q = 0; q < 8; q++) pv |= __ldg(&sw[2 * q + 1]);
    const bool is64 = (pv == 0u);

    // ---- CSR build ----
    for (int i = t; i < NN; i += T) oi[csr_word(i)] = 0;          // deg := 0
    gbar(oi);

    for (int e = t; e < EE; e += T)                               // histogram
        atomicAdd(&oi[csr_word(eidx(dst, e, is64))], 1);
    gbar(oi);

    // exclusive scan (blocked: thread t owns node t; high blocks idle here)
    __shared__ int wsum[16];
    __shared__ int sbase;
    const int lane = threadIdx.x & 31, wid = threadIdx.x >> 5;
    int v = (t < NN) ? __ldcg((const int*)&oi[csr_word(t)]) : 0;
    int incl = v;
    #pragma unroll
    for (int o = 1; o < 32; o <<= 1) {
        int tt = __shfl_up_sync(~0u, incl, o);
        if (lane >= o) incl += tt;
    }
    if (lane == 31) wsum[wid] = incl;
    __syncthreads();
    if (wid == 0) {
        int ws = (lane < 16) ? wsum[lane] : 0;
        #pragma unroll
        for (int o = 1; o < 16; o <<= 1) {
            int tt = __shfl_up_sync(~0u, ws, o);
            if (lane >= o) ws += tt;
        }
        if (lane < 16) wsum[lane] = ws;
    }
    __syncthreads();
    incl += wid ? wsum[wid - 1] : 0;
    if (threadIdx.x == 0) oi[csr_word(AUX_BASE + blockIdx.x)] = wsum[15];
    gbar(oi);
    {
        int part = 0;
        for (int j = threadIdx.x; j < blockIdx.x; j += TPB)
            part += __ldcg((const int*)&oi[csr_word(AUX_BASE + j)]);
        #pragma unroll
        for (int o = 16; o > 0; o >>= 1) part += __shfl_xor_sync(~0u, part, o);
        __syncthreads();              // wsum reuse
        if (lane == 0) wsum[wid] = part;
        __syncthreads();
        if (threadIdx.x == 0) {
            int s2 = 0;
            #pragma unroll
            for (int q = 0; q < 16; q++) s2 += wsum[q];
            sbase = s2;
        }
        __syncthreads();
    }
    if (t < NN) oi[csr_word(t)] = sbase + incl - v;               // cursor=rowptr
    gbar(oi);

    for (int e = t; e < EE; e += T) {                             // fill
        int d = eidx(dst, e, is64);
        int s = eidx(src, e, is64);
        int p = atomicAdd(&oi[csr_word(d)], 1);
        oi[csr_word(COL_BASE + p)] = s;
    }
    gbar(oi);

    // ---- hop engine: 2 threads per node, 8 cols each; bf16 iterates ----
    const int node = t >> 1;
    const int hf   = t & 1;                  // which half of the 16-col chunk
    const bool has = (node < NN);

    int rs = 0, re = 0;
    float ainv = 0.f;
    if (has) {
        re = __ldcg((const int*)&oi[csr_word(node)]);
        rs = node ? __ldcg((const int*)&oi[csr_word(node - 1)]) : 0;
        int dg = re - rs;
        ainv = (dg > 0) ? (ALPHA_C / (float)dg) : 0.f;
    }

    float def[8];
    #pragma unroll
    for (int q = 0; q < 8; q++) def[q] = 0.f;

    // chunk order: 0..5, 7 (h-iterate in region 6), 6 (in-place, last)
    #pragma unroll 1
    for (int ci = 0; ci < 8; ci++) {
        const int c  = (ci < 6) ? ci : (ci == 6 ? 7 : 6);
        const int hb = (c == 7) ? 6 : c;
        #pragma unroll 1
        for (int k = 1; k <= 4; k++) {
            float acc[8];
            #pragma unroll
            for (int q = 0; q < 8; q++) acc[q] = 0.f;
            if (has) {
                if (k == 1) {
                    // gather fp32 x (2x16B per thread per neighbor)
                    const float4* G = ((const float4*)x) + c * 4 + hf * 2;
                    for (int j = rs; j < re; j++) {
                        int s = __ldg((const int*)&oi[csr_word(COL_BASE + j)]);
                        const float4* r = G + (size_t)s * 32;
                        float4 a0 = __ldcg(r + 0);
                        float4 a1 = __ldcg(r + 1);
                        acc[0] += a0.x; acc[1] += a0.y; acc[2] += a0.z; acc[3] += a0.w;
                        acc[4] += a1.x; acc[5] += a1.y; acc[6] += a1.z; acc[7] += a1.w;
                    }
                } else {
                    // gather bf16 iterate (ONE 16B load per thread per neighbor)
                    const uint4* Gb = ((const uint4*)out) + hb * 4 + hf;
                    for (int j = rs; j < re; j++) {
                        int s = __ldg((const int*)&oi[csr_word(COL_BASE + j)]);
                        uint4 u = __ldcg(Gb + (size_t)s * 32);
                        __nv_bfloat162 b0 = *reinterpret_cast<__nv_bfloat162*>(&u.x);
                        __nv_bfloat162 b1 = *reinterpret_cast<__nv_bfloat162*>(&u.y);
                        __nv_bfloat162 b2 = *reinterpret_cast<__nv_bfloat162*>(&u.z);
                        __nv_bfloat162 b3 = *reinterpret_cast<__nv_bfloat162*>(&u.w);
                        float2 f0 = __bfloat1622float2(b0);
                        float2 f1 = __bfloat1622float2(b1);
                        float2 f2 = __bfloat1622float2(b2);
                        float2 f3 = __bfloat1622float2(b3);
                        acc[0] += f0.x; acc[1] += f0.y; acc[2] += f1.x; acc[3] += f1.y;
                        acc[4] += f2.x; acc[5] += f2.y; acc[6] += f3.x; acc[7] += f3.y;
                    }
                }
            }
            // barrier before writing iff write region == gather region
            if ((k == 2) || (k == 3) || (k == 4 && c != 7)) gbar(oi);
            if (has) {
                const float cx = (k == 4) ? BETA_C : 1.0f;
                const float4* xr = ((const float4*)x) + (size_t)node * 32 + c * 4 + hf * 2;
                float4 x0 = __ldg(xr + 0), x1 = __ldg(xr + 1);
                float vv[8];
                vv[0] = cx * x0.x + ainv * acc[0];
                vv[1] = cx * x0.y + ainv * acc[1];
                vv[2] = cx * x0.z + ainv * acc[2];
                vv[3] = cx * x0.w + ainv * acc[3];
                vv[4] = cx * x1.x + ainv * acc[4];
                vv[5] = cx * x1.y + ainv * acc[5];
                vv[6] = cx * x1.z + ainv * acc[6];
                vv[7] = cx * x1.w + ainv * acc[7];

                if (k < 4) {
                    // store bf16 iterate: 16B per thread, lower half of region hb
                    __nv_bfloat162 c0 = __float22bfloat162_rn(make_float2(vv[0], vv[1]));
                    __nv_bfloat162 c1 = __float22bfloat162_rn(make_float2(vv[2], vv[3]));
                    __nv_bfloat162 c2 = __float22bfloat162_rn(make_float2(vv[4], vv[5]));
                    __nv_bfloat162 c3 = __float22bfloat162_rn(make_float2(vv[6], vv[7]));
                    uint4 u;
                    u.x = *reinterpret_cast<unsigned*>(&c0);
                    u.y = *reinterpret_cast<unsigned*>(&c1);
                    u.z = *reinterpret_cast<unsigned*>(&c2);
                    u.w = *reinterpret_cast<unsigned*>(&c3);
                    ((uint4*)out)[(size_t)node * 32 + hb * 4 + hf] = u;
                } else if (c == 7 && node < 50000) {
                    #pragma unroll
                    for (int q = 0; q < 8; q++) def[q] = vv[q];   // defer over CSR
                } else {
                    float4* w = ((float4*)out) + (size_t)node * 32 + c * 4 + hf * 2;
                    w[0] = make_float4(vv[0], vv[1], vv[2], vv[3]);
                    w[1] = make_float4(vv[4], vv[5], vv[6], vv[7]);
                }
            }
            if (!(c == 6 && k == 4)) gbar(oi);   // last phase: no barrier
        }
    }

    // final: deferred chunk-7 outputs overwrite the CSR. Safe: the last CSR
    // reads happen in the chunk-6 k=4 gather, which completes before that
    // phase's pre-write barrier, which precedes this store.
    if (node < 50000) {
        float4* w = ((float4*)out) + (size_t)node * 32 + 28 + hf * 2;
        w[0] = make_float4(def[0], def[1], def[2], def[3]);
        w[1] = make_float4(def[4], def[5], def[6], def[7]);
    }
}

extern "C" void kernel_launch(void* const* d_in, const int* in_sizes, int n_in,
                              void* d_out, int out_size) {
    const float* x   = (const float*)d_in[0];
    const void*  src = d_in[1];
    const void*  dst = d_in[2];
    float*       out = (float*)d_out;
    (void)in_sizes; (void)n_in; (void)out_size;

    init_kernel<<<1, 32>>>(out);
    mgdcf_kernel<<<NBLK, TPB>>>(x, src, dst, out);
}